// round 3
// baseline (speedup 1.0000x reference)
#include <cuda_runtime.h>

#define BATCH 64
#define SEQ   512
#define DIN   512
#define MEMN  256
#define HID   512
#define BT    (BATCH*SEQ)        /* 32768 */
#define KTOT  1024
#define HN_OFF 16777216          /* BT*HID */

// ---------------- scratch (device globals: allocation-free) ----------------
__device__ float g_u[BT];                      // relu(x@Wu)
__device__ float g_Hcol[SEQ*MEMN];             // Hcol[t*256+k] = (A^t B)[k]
__device__ float g_Pa[MEMN*MEMN];
__device__ float g_Pb[MEMN*MEMN];
__device__ float g_Bcat[KTOT*HID];             // [G (512x512) ; Wh_x (512x512)]
__device__ float g_Acat[(size_t)BT*KTOT];      // [Toeplitz(u) | x]  (128 MB)

// ---------------- u = relu(x @ Wu_w + Wu_b) ----------------
__global__ void k_compute_u(const float* __restrict__ x,
                            const float* __restrict__ Wu,
                            const float* __restrict__ Wub) {
    int warp = (blockIdx.x * blockDim.x + threadIdx.x) >> 5;
    int lane = threadIdx.x & 31;
    if (warp >= BT) return;
    const float4* xr = (const float4*)(x + (size_t)warp * DIN);
    const float4* wr = (const float4*)Wu;
    float s = 0.f;
    #pragma unroll
    for (int j = lane; j < DIN/4; j += 32) {
        float4 a = xr[j], b = wr[j];
        s += a.x*b.x + a.y*b.y + a.z*b.z + a.w*b.w;
    }
    #pragma unroll
    for (int o = 16; o; o >>= 1) s += __shfl_xor_sync(0xffffffffu, s, o);
    if (lane == 0) g_u[warp] = fmaxf(s + Wub[0], 0.f);
}

// ---------------- first 16 columns of H sequentially ----------------
__global__ void k_seq16(const float* __restrict__ A, const float* __restrict__ Bv) {
    __shared__ float sh[MEMN];
    int k = threadIdx.x;
    sh[k] = Bv[k];
    __syncthreads();
    for (int t = 0; t < 16; t++) {
        g_Hcol[t*MEMN + k] = sh[k];
        const float* Ar = A + k*MEMN;
        float v = 0.f;
        #pragma unroll 8
        for (int j = 0; j < MEMN; j++) v += Ar[j] * sh[j];
        __syncthreads();
        sh[k] = v;
        __syncthreads();
    }
}

// ---------------- C = X @ Y, all 256x256 ----------------
__global__ void k_mm256(float* __restrict__ C, const float* __restrict__ X,
                        const float* __restrict__ Y) {
    __shared__ float sX[16][17], sY[16][17];
    int tx = threadIdx.x, ty = threadIdx.y;
    int row = blockIdx.y*16 + ty, col = blockIdx.x*16 + tx;
    float acc = 0.f;
    for (int kt = 0; kt < 256; kt += 16) {
        sX[ty][tx] = X[row*256 + kt + tx];
        sY[ty][tx] = Y[(kt + ty)*256 + col];
        __syncthreads();
        #pragma unroll
        for (int k = 0; k < 16; k++) acc += sX[ty][k] * sY[k][tx];
        __syncthreads();
    }
    C[row*256 + col] = acc;
}

// ---------------- Hcol[n+c] = P @ Hcol[c], c in [0,n) ----------------
__global__ void k_apply(const float* __restrict__ P, int n) {
    __shared__ float s[MEMN];
    int k = threadIdx.x;
    int c = blockIdx.x;
    s[k] = g_Hcol[c*MEMN + k];
    __syncthreads();
    const float* Pr = P + k*MEMN;
    float v = 0.f;
    #pragma unroll 8
    for (int j = 0; j < MEMN; j++) v += Pr[j] * s[j];
    g_Hcol[(n + c)*MEMN + k] = v;
}

// ---------------- G[d][j] = sum_k Hcol[d][k] * Wh_w[k][j]  (rows 0..255) ----
__global__ void k_buildG(const float* __restrict__ Whw) {
    __shared__ float sX[16][17], sY[16][17];
    int tx = threadIdx.x, ty = threadIdx.y;
    int row = blockIdx.y*16 + ty;   // d
    int col = blockIdx.x*16 + tx;   // j
    float acc = 0.f;
    for (int kt = 0; kt < 256; kt += 16) {
        sX[ty][tx] = g_Hcol[row*256 + kt + tx];
        sY[ty][tx] = Whw[(kt + ty)*HID + col];
        __syncthreads();
        #pragma unroll
        for (int k = 0; k < 16; k++) acc += sX[ty][k] * sY[k][tx];
        __syncthreads();
    }
    g_Bcat[row*HID + col] = acc;
}

// ---------------- Bcat rows 512..1023 = Wh_w rows 256..767 ----------------
__global__ void k_copyWhx(const float* __restrict__ Whw) {
    int e = blockIdx.x * blockDim.x + threadIdx.x;      // over 65536 float4
    if (e >= (512*512)/4) return;
    ((float4*)g_Bcat)[ (512*512)/4 + e ] = ((const float4*)(Whw + 256*512))[e];
}

// ---------------- Acat = [Toeplitz(u) | x] ----------------
__global__ void k_buildAcat(const float* __restrict__ x) {
    int e4 = blockIdx.x * blockDim.x + threadIdx.x;     // over BT*KTOT/4
    if (e4 >= BT*(KTOT/4)) return;
    int d4  = (e4 & 255) * 4;
    int row = e4 >> 8;
    float4 v;
    if (d4 < 512) {
        int t = row & 511;
        const float* ub = g_u + (row >> 9) * 512;
        v.x = (d4     <= t) ? ub[t - d4    ] : 0.f;
        v.y = (d4 + 1 <= t) ? ub[t - d4 - 1] : 0.f;
        v.z = (d4 + 2 <= t) ? ub[t - d4 - 2] : 0.f;
        v.w = (d4 + 3 <= t) ? ub[t - d4 - 3] : 0.f;
    } else {
        v = *(const float4*)(x + (size_t)row * DIN + (d4 - 512));
    }
    *(float4*)(g_Acat + (size_t)row * KTOT + d4) = v;
}

// ---------------- main GEMM: h = relu(Acat @ Bcat + b), +h_n epilogue ------
// M=32768 N=512 K=1024, tiles 128x128x8, 256 threads, 8x8 per thread.
__global__ __launch_bounds__(256, 2)
void k_sgemm(const float* __restrict__ Ag, const float* __restrict__ Bg,
             const float* __restrict__ bias, float* __restrict__ out) {
    __shared__ float As[8][128];
    __shared__ float Bs[8][128];
    int bx = blockIdx.x;           // 0..3   (N)
    int by = blockIdx.y;           // 0..255 (M)
    int tid = threadIdx.x;
    int tx = tid & 15, ty = tid >> 4;

    const float* Aptr = Ag + (size_t)(by * 128) * KTOT;
    const float* Bptr = Bg + bx * 128;

    int arow = tid >> 1, ac = (tid & 1) * 4;
    int brow = tid >> 5, bc = (tid & 31) * 4;

    float acc[8][8];
    #pragma unroll
    for (int i = 0; i < 8; i++)
        #pragma unroll
        for (int j = 0; j < 8; j++) acc[i][j] = 0.f;

    for (int kt = 0; kt < KTOT; kt += 8) {
        float4 av = *(const float4*)(Aptr + arow*KTOT + kt + ac);
        float4 bv = *(const float4*)(Bptr + (kt + brow)*HID + bc);
        As[ac+0][arow] = av.x; As[ac+1][arow] = av.y;
        As[ac+2][arow] = av.z; As[ac+3][arow] = av.w;
        *(float4*)&Bs[brow][bc] = bv;
        __syncthreads();
        #pragma unroll
        for (int k = 0; k < 8; k++) {
            float4 a0 = *(float4*)&As[k][ty*8];
            float4 a1 = *(float4*)&As[k][ty*8 + 4];
            float4 b0 = *(float4*)&Bs[k][tx*8];
            float4 b1 = *(float4*)&Bs[k][tx*8 + 4];
            float a[8] = {a0.x,a0.y,a0.z,a0.w,a1.x,a1.y,a1.z,a1.w};
            float b[8] = {b0.x,b0.y,b0.z,b0.w,b1.x,b1.y,b1.z,b1.w};
            #pragma unroll
            for (int i = 0; i < 8; i++)
                #pragma unroll
                for (int j = 0; j < 8; j++) acc[i][j] += a[i] * b[j];
        }
        __syncthreads();
    }

    int gr0 = by*128 + ty*8;
    int gc0 = bx*128 + tx*8;
    float bb[8];
    #pragma unroll
    for (int j = 0; j < 8; j++) bb[j] = bias[gc0 + j];
    #pragma unroll
    for (int i = 0; i < 8; i++) {
        int row = gr0 + i;
        float4 v0, v1;
        v0.x = fmaxf(acc[i][0]+bb[0], 0.f); v0.y = fmaxf(acc[i][1]+bb[1], 0.f);
        v0.z = fmaxf(acc[i][2]+bb[2], 0.f); v0.w = fmaxf(acc[i][3]+bb[3], 0.f);
        v1.x = fmaxf(acc[i][4]+bb[4], 0.f); v1.y = fmaxf(acc[i][5]+bb[5], 0.f);
        v1.z = fmaxf(acc[i][6]+bb[6], 0.f); v1.w = fmaxf(acc[i][7]+bb[7], 0.f);
        *(float4*)(out + (size_t)row*HID + gc0)     = v0;
        *(float4*)(out + (size_t)row*HID + gc0 + 4) = v1;
        if ((row & 511) == 511) {
            int b = row >> 9;
            *(float4*)(out + HN_OFF + (size_t)b*HID + gc0)     = v0;
            *(float4*)(out + HN_OFF + (size_t)b*HID + gc0 + 4) = v1;
        }
    }
}

// ---------------------------------------------------------------------------
extern "C" void kernel_launch(void* const* d_in, const int* in_sizes, int n_in,
                              void* d_out, int out_size) {
    const float* x    = (const float*)d_in[0];
    const float* Wu_w = (const float*)d_in[1];
    const float* Wu_b = (const float*)d_in[2];
    const float* Wh_w = (const float*)d_in[3];
    const float* Wh_b = (const float*)d_in[4];
    const float* A    = (const float*)d_in[5];
    const float* Bv   = (const float*)d_in[6];
    float* out = (float*)d_out;

    float *pa, *pb, *pacat, *pbcat;
    cudaGetSymbolAddress((void**)&pa, g_Pa);
    cudaGetSymbolAddress((void**)&pb, g_Pb);
    cudaGetSymbolAddress((void**)&pacat, g_Acat);
    cudaGetSymbolAddress((void**)&pbcat, g_Bcat);

    dim3 b16(16,16), g16(16,16);

    k_compute_u<<<4096, 256>>>(x, Wu_w, Wu_b);
    k_seq16<<<1, 256>>>(A, Bv);

    // power-doubling chain for H
    k_mm256<<<g16, b16>>>(pb, A,  A );   // A^2
    k_mm256<<<g16, b16>>>(pa, pb, pb);   // A^4
    k_mm256<<<g16, b16>>>(pb, pa, pa);   // A^8
    k_mm256<<<g16, b16>>>(pa, pb, pb);   // A^16
    k_apply<<<16,  256>>>(pa, 16);
    k_mm256<<<g16, b16>>>(pb, pa, pa);   // A^32
    k_apply<<<32,  256>>>(pb, 32);
    k_mm256<<<g16, b16>>>(pa, pb, pb);   // A^64
    k_apply<<<64,  256>>>(pa, 64);
    k_mm256<<<g16, b16>>>(pb, pa, pa);   // A^128
    k_apply<<<128, 256>>>(pb, 128);
    k_mm256<<<g16, b16>>>(pa, pb, pb);   // A^256
    k_apply<<<256, 256>>>(pa, 256);

    k_buildG<<<dim3(32,32), b16>>>(Wh_w);
    k_copyWhx<<<256, 256>>>(Wh_w);
    k_buildAcat<<<32768, 256>>>(x);

    k_sgemm<<<dim3(4, 256), 256>>>(pacat, pbcat, Wh_b, out);
}

// round 8
// speedup vs baseline: 2.3458x; 2.3458x over previous
#include <cuda_runtime.h>
#include <cuda_bf16.h>
#include <cstdint>

#define BATCH 64
#define SEQ   512
#define DIN   512
#define MEMN  256
#define HID   512
#define BT    (BATCH*SEQ)        /* 32768 */
#define KTOT  1024
#define HN_OFF 16777216          /* BT*HID */

// ---------------- scratch (device globals: allocation-free) ----------------
__device__ float g_u[BT];                       // relu(x@Wu)
__device__ float g_Hcol[SEQ*MEMN];              // Hcol[t*256+k] = (A^t B)[k]
__device__ float g_Pa[MEMN*MEMN];
__device__ float g_Pb[MEMN*MEMN];
__device__ float g_Bcat[KTOT*HID];              // [G (512x512) ; Wh_x (512x512)]
__device__ __align__(16) __nv_bfloat16 g_Ahi[(size_t)BT*KTOT];  // 64 MB
__device__ __align__(16) __nv_bfloat16 g_Alo[(size_t)BT*KTOT];  // 64 MB
__device__ __align__(16) __nv_bfloat16 g_Bth[HID*KTOT];         // B^T hi (N x K)
__device__ __align__(16) __nv_bfloat16 g_Btl[HID*KTOT];         // B^T lo

// ====================== PTX helpers (base ISA only) ========================
__device__ __forceinline__ uint32_t smem_u32(const void* p) {
    uint32_t a;
    asm("{ .reg .u64 t; cvta.to.shared.u64 t, %1; cvt.u32.u64 %0, t; }"
        : "=r"(a) : "l"(p));
    return a;
}
__device__ __forceinline__ void cpa16(uint32_t s, const void* g) {
    asm volatile("cp.async.cg.shared.global [%0], [%1], 16;" :: "r"(s), "l"(g));
}
#define CP_COMMIT()  asm volatile("cp.async.commit_group;" ::: "memory")
#define CP_WAIT1()   asm volatile("cp.async.wait_group 1;" ::: "memory")

__device__ __forceinline__ void ldsm4(uint32_t* r, uint32_t a) {
    asm volatile("ldmatrix.sync.aligned.m8n8.x4.shared.b16 {%0,%1,%2,%3}, [%4];"
        : "=r"(r[0]), "=r"(r[1]), "=r"(r[2]), "=r"(r[3]) : "r"(a));
}
__device__ __forceinline__ void mma16816(float* c, const uint32_t* a, const uint32_t* b) {
    asm volatile("mma.sync.aligned.m16n8k16.row.col.f32.bf16.bf16.f32 "
        "{%0,%1,%2,%3}, {%4,%5,%6,%7}, {%8,%9}, {%0,%1,%2,%3};"
        : "+f"(c[0]), "+f"(c[1]), "+f"(c[2]), "+f"(c[3])
        : "r"(a[0]), "r"(a[1]), "r"(a[2]), "r"(a[3]), "r"(b[0]), "r"(b[1]));
}

// ---------------- u = relu(x @ Wu_w + Wu_b) ----------------
__global__ void k_compute_u(const float* __restrict__ x,
                            const float* __restrict__ Wu,
                            const float* __restrict__ Wub) {
    int warp = (blockIdx.x * blockDim.x + threadIdx.x) >> 5;
    int lane = threadIdx.x & 31;
    if (warp >= BT) return;
    const float4* xr = (const float4*)(x + (size_t)warp * DIN);
    const float4* wr = (const float4*)Wu;
    float s = 0.f;
    #pragma unroll
    for (int j = lane; j < DIN/4; j += 32) {
        float4 a = xr[j], b = wr[j];
        s += a.x*b.x + a.y*b.y + a.z*b.z + a.w*b.w;
    }
    #pragma unroll
    for (int o = 16; o; o >>= 1) s += __shfl_xor_sync(0xffffffffu, s, o);
    if (lane == 0) g_u[warp] = fmaxf(s + Wub[0], 0.f);
}

// ---------------- first 16 columns of H sequentially ----------------
__global__ void k_seq16(const float* __restrict__ A, const float* __restrict__ Bv) {
    __shared__ float sh[MEMN];
    int k = threadIdx.x;
    sh[k] = Bv[k];
    __syncthreads();
    for (int t = 0; t < 16; t++) {
        g_Hcol[t*MEMN + k] = sh[k];
        const float* Ar = A + k*MEMN;
        float v = 0.f;
        #pragma unroll 8
        for (int j = 0; j < MEMN; j++) v += Ar[j] * sh[j];
        __syncthreads();
        sh[k] = v;
        __syncthreads();
    }
}

// ---------------- C = X @ Y, all 256x256 ----------------
__global__ void k_mm256(float* __restrict__ C, const float* __restrict__ X,
                        const float* __restrict__ Y) {
    __shared__ float sX[16][17], sY[16][17];
    int tx = threadIdx.x, ty = threadIdx.y;
    int row = blockIdx.y*16 + ty, col = blockIdx.x*16 + tx;
    float acc = 0.f;
    for (int kt = 0; kt < 256; kt += 16) {
        sX[ty][tx] = X[row*256 + kt + tx];
        sY[ty][tx] = Y[(kt + ty)*256 + col];
        __syncthreads();
        #pragma unroll
        for (int k = 0; k < 16; k++) acc += sX[ty][k] * sY[k][tx];
        __syncthreads();
    }
    C[row*256 + col] = acc;
}

// ---------------- Hcol[n+c] = P @ Hcol[c], c in [0,n) ----------------
__global__ void k_apply(const float* __restrict__ P, int n) {
    __shared__ float s[MEMN];
    int k = threadIdx.x;
    int c = blockIdx.x;
    s[k] = g_Hcol[c*MEMN + k];
    __syncthreads();
    const float* Pr = P + k*MEMN;
    float v = 0.f;
    #pragma unroll 8
    for (int j = 0; j < MEMN; j++) v += Pr[j] * s[j];
    g_Hcol[(n + c)*MEMN + k] = v;
}

// -------- fused: blocks [0,n) apply Pin; blocks [n, n+256) Pout = Pin*Pin ---
__global__ void k_mm_apply(float* __restrict__ Pout, const float* __restrict__ Pin, int n) {
    int b = blockIdx.x;
    int tid = threadIdx.x;
    if (b < n) {
        __shared__ float s[MEMN];
        int k = tid;
        s[k] = g_Hcol[b*MEMN + k];
        __syncthreads();
        const float* Pr = Pin + k*MEMN;
        float v = 0.f;
        #pragma unroll 8
        for (int j = 0; j < MEMN; j++) v += Pr[j] * s[j];
        g_Hcol[(n + b)*MEMN + k] = v;
    } else {
        __shared__ float sX[16][17], sY[16][17];
        int bb = b - n;
        int tx = tid & 15, ty = tid >> 4;
        int row = (bb >> 4)*16 + ty, col = (bb & 15)*16 + tx;
        float acc = 0.f;
        for (int kt = 0; kt < 256; kt += 16) {
            sX[ty][tx] = Pin[row*256 + kt + tx];
            sY[ty][tx] = Pin[(kt + ty)*256 + col];
            __syncthreads();
            #pragma unroll
            for (int k = 0; k < 16; k++) acc += sX[ty][k] * sY[k][tx];
            __syncthreads();
        }
        Pout[row*256 + col] = acc;
    }
}

// ---------------- G[d][j] = sum_k Hcol[d][k] * Wh_w[k][j]  (rows 0..255) ----
__global__ void k_buildG(const float* __restrict__ Whw) {
    __shared__ float sX[16][17], sY[16][17];
    int tx = threadIdx.x, ty = threadIdx.y;
    int row = blockIdx.y*16 + ty;
    int col = blockIdx.x*16 + tx;
    float acc = 0.f;
    for (int kt = 0; kt < 256; kt += 16) {
        sX[ty][tx] = g_Hcol[row*256 + kt + tx];
        sY[ty][tx] = Whw[(kt + ty)*HID + col];
        __syncthreads();
        #pragma unroll
        for (int k = 0; k < 16; k++) acc += sX[ty][k] * sY[k][tx];
        __syncthreads();
    }
    g_Bcat[row*HID + col] = acc;
}

// ---------------- Bcat rows 512..1023 = Wh_w rows 256..767 ----------------
__global__ void k_copyWhx(const float* __restrict__ Whw) {
    int e = blockIdx.x * blockDim.x + threadIdx.x;
    if (e >= (512*512)/4) return;
    ((float4*)g_Bcat)[ (512*512)/4 + e ] = ((const float4*)(Whw + 256*512))[e];
}

// ------- split Bcat into transposed bf16 hi/lo: Bth[n][k] = hi(Bcat[k][n]) --
__global__ void k_splitB() {
    int e = blockIdx.x * blockDim.x + threadIdx.x;
    if (e >= HID*KTOT) return;
    int n = e >> 10, k = e & 1023;
    float v = g_Bcat[k*HID + n];
    __nv_bfloat16 h = __float2bfloat16_rn(v);
    g_Bth[(size_t)n*KTOT + k] = h;
    g_Btl[(size_t)n*KTOT + k] = __float2bfloat16_rn(v - __bfloat162float(h));
}

// ------- build split Toeplitz/x operand: Ahi/Alo[r][d], row-major bf16 ------
__global__ void k_splitA(const float* __restrict__ x) {
    int e4 = blockIdx.x * blockDim.x + threadIdx.x;     // over BT*256
    if (e4 >= BT*(KTOT/4)) return;
    int d4  = (e4 & 255) * 4;
    int row = e4 >> 8;
    float v0, v1, v2, v3;
    if (d4 < 512) {
        int t = row & 511;
        const float* ub = g_u + (row >> 9) * 512;
        v0 = (d4     <= t) ? ub[t - d4    ] : 0.f;
        v1 = (d4 + 1 <= t) ? ub[t - d4 - 1] : 0.f;
        v2 = (d4 + 2 <= t) ? ub[t - d4 - 2] : 0.f;
        v3 = (d4 + 3 <= t) ? ub[t - d4 - 3] : 0.f;
    } else {
        float4 xv = *(const float4*)(x + (size_t)row * DIN + (d4 - 512));
        v0 = xv.x; v1 = xv.y; v2 = xv.z; v3 = xv.w;
    }
    __nv_bfloat16 h0 = __float2bfloat16_rn(v0), h1 = __float2bfloat16_rn(v1);
    __nv_bfloat16 h2 = __float2bfloat16_rn(v2), h3 = __float2bfloat16_rn(v3);
    ushort4 hv, lv;
    hv.x = __bfloat16_as_ushort(h0); hv.y = __bfloat16_as_ushort(h1);
    hv.z = __bfloat16_as_ushort(h2); hv.w = __bfloat16_as_ushort(h3);
    lv.x = __bfloat16_as_ushort(__float2bfloat16_rn(v0 - __bfloat162float(h0)));
    lv.y = __bfloat16_as_ushort(__float2bfloat16_rn(v1 - __bfloat162float(h1)));
    lv.z = __bfloat16_as_ushort(__float2bfloat16_rn(v2 - __bfloat162float(h2)));
    lv.w = __bfloat16_as_ushort(__float2bfloat16_rn(v3 - __bfloat162float(h3)));
    size_t off = (size_t)row * KTOT + d4;
    *(ushort4*)((unsigned short*)g_Ahi + off) = hv;
    *(ushort4*)((unsigned short*)g_Alo + off) = lv;
}

// ================= mma.sync main GEMM (no tcgen05) =========================
// C(32768x512) = A(32768x1024) @ B(1024x512);  C = AhBh + AhBl + AlBh
// CTA 128x128, 8 warps (2x4), warp 64x32, K-chunk 32, 2-stage cp.async.
#define KCH      32
#define NCHK     (KTOT/KCH)        /* 32 */
#define ASTR     80                /* padded row stride: 64B data + 16B pad */
#define HALF_REG 10240             /* 128 rows * 80B */
#define REGION   20480             /* hi + lo */
#define STAGE    40960             /* A region + B region */
#define MM_SMEM  (2*STAGE)         /* 81920 */

__device__ __forceinline__ void mm_loads(
    uint32_t base, int tid, int chunk,
    const __nv_bfloat16* __restrict__ Ah, const __nv_bfloat16* __restrict__ Al,
    const __nv_bfloat16* __restrict__ Bh, const __nv_bfloat16* __restrict__ Bl,
    size_t arow0, size_t nrow0)
{
    size_t koff = (size_t)chunk * KCH;
    #pragma unroll
    for (int it = 0; it < 8; it++) {
        int u = tid + it * 256;                 // 0..2047
        int j    = u & 3;                       // 16B chunk in row
        int r    = (u >> 2) & 127;              // row in half
        int half = (u >> 9) & 1;                // 0=hi 1=lo
        const __nv_bfloat16* src;
        uint32_t dst;
        if (u < 1024) {                         // A (uniform per it)
            src = (half ? Al : Ah) + (arow0 + r) * KTOT + koff + j*8;
            dst = base + half*HALF_REG + r*ASTR + j*16;
        } else {                                // B
            src = (half ? Bl : Bh) + (nrow0 + r) * KTOT + koff + j*8;
            dst = base + REGION + half*HALF_REG + r*ASTR + j*16;
        }
        cpa16(dst, src);
    }
}

__global__ __launch_bounds__(256, 2)
void k_mmagemm(const __nv_bfloat16* __restrict__ Ah, const __nv_bfloat16* __restrict__ Al,
               const __nv_bfloat16* __restrict__ Bh, const __nv_bfloat16* __restrict__ Bl,
               const float* __restrict__ bias, float* __restrict__ out)
{
    extern __shared__ char smem[];
    uint32_t sbase = smem_u32(smem);
    int tid = threadIdx.x, wid = tid >> 5, lane = tid & 31;
    size_t arow0 = (size_t)blockIdx.y * 128;
    size_t nrow0 = (size_t)blockIdx.x * 128;

    mm_loads(sbase,         tid, 0, Ah, Al, Bh, Bl, arow0, nrow0); CP_COMMIT();
    mm_loads(sbase + STAGE, tid, 1, Ah, Al, Bh, Bl, arow0, nrow0); CP_COMMIT();

    float acc[4][4][4];
    #pragma unroll
    for (int i = 0; i < 4; i++)
        #pragma unroll
        for (int j = 0; j < 4; j++)
            #pragma unroll
            for (int q = 0; q < 4; q++) acc[i][j][q] = 0.f;

    int wm = wid >> 2, wn = wid & 3;
    int m0 = wm * 64, n0 = wn * 32;
    uint32_t grp = lane >> 3, lrow = lane & 7;
    // ldmatrix lane address offsets (within region):
    uint32_t a_off = (uint32_t)(m0 + lrow + ((grp & 1) << 3)) * ASTR + ((grp >> 1) << 4);
    uint32_t b_off = (uint32_t)(n0 + lrow + ((grp & 2) << 2)) * ASTR + ((grp & 1) << 4);

    for (int ch = 0; ch < NCHK; ch++) {
        uint32_t ab = sbase + (uint32_t)(ch & 1) * STAGE;
        uint32_t bb = ab + REGION;
        CP_WAIT1();
        __syncthreads();
        #pragma unroll
        for (int s = 0; s < 2; s++) {
            uint32_t bhf[4][2], blf[4][2];
            #pragma unroll
            for (int p = 0; p < 2; p++) {
                uint32_t ba = bb + b_off + (uint32_t)p*16*ASTR + (uint32_t)s*32;
                uint32_t t4[4];
                ldsm4(t4, ba);
                bhf[2*p][0]=t4[0]; bhf[2*p][1]=t4[1];
                bhf[2*p+1][0]=t4[2]; bhf[2*p+1][1]=t4[3];
                ldsm4(t4, ba + HALF_REG);
                blf[2*p][0]=t4[0]; blf[2*p][1]=t4[1];
                blf[2*p+1][0]=t4[2]; blf[2*p+1][1]=t4[3];
            }
            #pragma unroll
            for (int i = 0; i < 4; i++) {
                uint32_t aa = ab + a_off + (uint32_t)i*16*ASTR + (uint32_t)s*32;
                uint32_t ah4[4], al4[4];
                ldsm4(ah4, aa);
                ldsm4(al4, aa + HALF_REG);
                #pragma unroll
                for (int j = 0; j < 4; j++) {
                    mma16816(acc[i][j], ah4, bhf[j]);
                    mma16816(acc[i][j], ah4, blf[j]);
                    mma16816(acc[i][j], al4, bhf[j]);
                }
            }
        }
        __syncthreads();
        if (ch + 2 < NCHK)
            mm_loads(ab, tid, ch + 2, Ah, Al, Bh, Bl, arow0, nrow0);
        CP_COMMIT();
    }

    // ---- epilogue: bias + relu + store h (+ h_n for last row of each seq) --
    #pragma unroll
    for (int i = 0; i < 4; i++) {
        int rbase = (int)arow0 + m0 + i*16 + (lane >> 2);
        #pragma unroll
        for (int hh = 0; hh < 2; hh++) {
            int r = rbase + hh*8;
            float* orow = out + (size_t)r * HID;
            bool last = ((r & 511) == 511);
            float* hrow = out + HN_OFF + (size_t)(r >> 9) * HID;
            #pragma unroll
            for (int j = 0; j < 4; j++) {
                int col = (int)nrow0 + n0 + j*8 + (lane & 3)*2;
                float2 v;
                v.x = fmaxf(acc[i][j][hh*2+0] + bias[col],     0.f);
                v.y = fmaxf(acc[i][j][hh*2+1] + bias[col + 1], 0.f);
                *(float2*)(orow + col) = v;
                if (last) *(float2*)(hrow + col) = v;
            }
        }
    }
}

// ---------------------------------------------------------------------------
extern "C" void kernel_launch(void* const* d_in, const int* in_sizes, int n_in,
                              void* d_out, int out_size) {
    const float* x    = (const float*)d_in[0];
    const float* Wu_w = (const float*)d_in[1];
    const float* Wu_b = (const float*)d_in[2];
    const float* Wh_w = (const float*)d_in[3];
    const float* Wh_b = (const float*)d_in[4];
    const float* A    = (const float*)d_in[5];
    const float* Bv   = (const float*)d_in[6];
    float* out = (float*)d_out;

    float *pa, *pb;
    __nv_bfloat16 *ah, *al, *bh, *bl;
    cudaGetSymbolAddress((void**)&pa, g_Pa);
    cudaGetSymbolAddress((void**)&pb, g_Pb);
    cudaGetSymbolAddress((void**)&ah, g_Ahi);
    cudaGetSymbolAddress((void**)&al, g_Alo);
    cudaGetSymbolAddress((void**)&bh, g_Bth);
    cudaGetSymbolAddress((void**)&bl, g_Btl);

    cudaFuncSetAttribute(k_mmagemm, cudaFuncAttributeMaxDynamicSharedMemorySize, MM_SMEM);

    dim3 b16(16,16), g16(16,16);

    k_compute_u<<<4096, 256>>>(x, Wu_w, Wu_b);
    k_splitA<<<32768, 256>>>(x);

    k_seq16<<<1, 256>>>(A, Bv);
    // power-doubling chain for H (apply fused with next squaring)
    k_mm256<<<g16, b16>>>(pb, A,  A );           // A^2
    k_mm256<<<g16, b16>>>(pa, pb, pb);           // A^4
    k_mm256<<<g16, b16>>>(pb, pa, pa);           // A^8
    k_mm256<<<g16, b16>>>(pa, pb, pb);           // A^16
    k_mm_apply<<<16  + 256, 256>>>(pb, pa, 16);  // cols[16:32) ; A^32
    k_mm_apply<<<32  + 256, 256>>>(pa, pb, 32);  // cols[32:64) ; A^64
    k_mm_apply<<<64  + 256, 256>>>(pb, pa, 64);  // cols[64:128); A^128
    k_mm_apply<<<128 + 256, 256>>>(pa, pb, 128); // cols[128:256); A^256
    k_apply<<<256, 256>>>(pa, 256);              // cols[256:512)

    k_buildG<<<dim3(32,32), b16>>>(Wh_w);
    k_copyWhx<<<256, 256>>>(Wh_w);
    k_splitB<<<2048, 256>>>();

    k_mmagemm<<<dim3(4, 256), 256, MM_SMEM>>>(ah, al, bh, bl, Wh_b, out);
}